// round 2
// baseline (speedup 1.0000x reference)
#include <cuda_runtime.h>
#include <math.h>

#define DIM 512
#define MARGIN 1.0f
#define RULE_WEIGHT 0.5f

#define MAX_B 1024

// Per-block partial sums (allocation-free scratch)
__device__ float g_basic[MAX_B];
__device__ float g_rulep[MAX_B];

__device__ __forceinline__ float warp_red(float v) {
#pragma unroll
    for (int o = 16; o; o >>= 1) v += __shfl_xor_sync(0xffffffffu, v, o);
    return v;
}

// TransH distance, he/te register-resident (warp-collective).
// d = || (he - te + re) - c*w ||,  c = (he.w - te.w)/(w.w)
__device__ __forceinline__ float dist_from_regs(
    const float4 he[4], const float4 te[4],
    const float* __restrict__ rel, const float* __restrict__ nv,
    int r, int lane)
{
    const float4* w4  = reinterpret_cast<const float4*>(nv  + (size_t)r * DIM);
    const float4* re4 = reinterpret_cast<const float4*>(rel + (size_t)r * DIM);
    float4 w[4], re[4];
    float ww = 0.f, hw = 0.f, tw = 0.f;
#pragma unroll
    for (int i = 0; i < 4; i++) {
        w[i]  = w4[lane + 32 * i];
        re[i] = re4[lane + 32 * i];
        ww += w[i].x * w[i].x + w[i].y * w[i].y + w[i].z * w[i].z + w[i].w * w[i].w;
        hw += he[i].x * w[i].x + he[i].y * w[i].y + he[i].z * w[i].z + he[i].w * w[i].w;
        tw += te[i].x * w[i].x + te[i].y * w[i].y + te[i].z * w[i].z + te[i].w * w[i].w;
    }
    ww = warp_red(ww);
    hw = warp_red(hw);
    tw = warp_red(tw);
    float c = (hw - tw) / ww;
    float ss = 0.f;
#pragma unroll
    for (int i = 0; i < 4; i++) {
        float dx = he[i].x - te[i].x + re[i].x - c * w[i].x;
        float dy = he[i].y - te[i].y + re[i].y - c * w[i].y;
        float dz = he[i].z - te[i].z + re[i].z - c * w[i].z;
        float dw = he[i].w - te[i].w + re[i].w - c * w[i].w;
        ss += dx * dx + dy * dy + dz * dz + dw * dw;
    }
    ss = warp_red(ss);
    return sqrtf(ss);
}

// One block per pos triple: warp 0 = pos distance + rule terms,
// warps 1..ratio = the ratio negs paired with this pos. The margin-loss
// pairing is resolved block-locally in smem; block writes two partials.
__global__ void fused_kernel(
    const int* __restrict__ pos, const int* __restrict__ neg,
    const int* __restrict__ rr1, const int* __restrict__ rr2,
    const float* __restrict__ rconf,
    const float* __restrict__ ent, const float* __restrict__ rel,
    const float* __restrict__ nv,
    int ratio, int NR)
{
    __shared__ float s_dpos;
    __shared__ float s_rule;
    __shared__ float s_dneg[31];

    int wid  = threadIdx.x >> 5;
    int lane = threadIdx.x & 31;
    int b    = blockIdx.x;

    int h, r, t;
    if (wid == 0) {
        h = pos[3 * b]; r = pos[3 * b + 1]; t = pos[3 * b + 2];
    } else {
        int k = b * ratio + (wid - 1);
        h = neg[3 * k]; r = neg[3 * k + 1]; t = neg[3 * k + 2];
    }

    const float4* he4 = reinterpret_cast<const float4*>(ent + (size_t)h * DIM);
    const float4* te4 = reinterpret_cast<const float4*>(ent + (size_t)t * DIM);
    float4 he[4], te[4];
#pragma unroll
    for (int i = 0; i < 4; i++) {
        he[i] = he4[lane + 32 * i];
        te[i] = te4[lane + 32 * i];
    }

    float d = dist_from_regs(he, te, rel, nv, r, lane);

    if (wid == 0) {
        // Rule terms: only rules with rule_r1[j] == r contribute a non-zero
        // (mask * conf * score); everything else is exactly zero — skip.
        float racc = 0.f;
        for (int j = 0; j < NR; j++) {
            if (rr1[j] == r)
                racc += rconf[j] * dist_from_regs(he, te, rel, nv, rr2[j], lane);
        }
        if (lane == 0) { s_dpos = d; s_rule = racc; }
    } else {
        if (lane == 0) s_dneg[wid - 1] = d;
    }
    __syncthreads();

    if (threadIdx.x == 0) {
        float dp = s_dpos;
        float acc = 0.f;
        for (int j = 0; j < ratio; j++) {
            float v = MARGIN + dp - s_dneg[j];
            acc += (v > 0.f) ? v : 0.f;
        }
        g_basic[b] = acc;
        g_rulep[b] = s_rule;
    }
}

// Sum 2*B partials. Vectorized: one float4 per thread per array -> full MLP,
// one latency round, launch-overhead bound.
__global__ void __launch_bounds__(256)
final_reduce(float* __restrict__ out, int B, int NEG)
{
    __shared__ float sb[256];
    __shared__ float sr[256];
    int tid = threadIdx.x;

    float acc = 0.f, racc = 0.f;
    const float4* b4 = reinterpret_cast<const float4*>(g_basic);
    const float4* r4 = reinterpret_cast<const float4*>(g_rulep);
    int n4 = B >> 2;
    for (int i = tid; i < n4; i += 256) {
        float4 v = b4[i];
        acc += v.x + v.y + v.z + v.w;
        float4 u = r4[i];
        racc += u.x + u.y + u.z + u.w;
    }
    // tail (B not multiple of 4)
    for (int i = (n4 << 2) + tid; i < B; i += 256) {
        acc += g_basic[i];
        racc += g_rulep[i];
    }

    sb[tid] = acc; sr[tid] = racc;
    __syncthreads();
    for (int s = 128; s; s >>= 1) {
        if (tid < s) { sb[tid] += sb[tid + s]; sr[tid] += sr[tid + s]; }
        __syncthreads();
    }
    if (tid == 0)
        out[0] = sb[0] / (float)NEG + RULE_WEIGHT * sr[0];
}

extern "C" void kernel_launch(void* const* d_in, const int* in_sizes, int n_in,
                              void* d_out, int out_size)
{
    const int*   pos   = (const int*)d_in[0];
    const int*   neg   = (const int*)d_in[1];
    const int*   rr1   = (const int*)d_in[2];
    const int*   rr2   = (const int*)d_in[3];
    const float* rconf = (const float*)d_in[4];
    const float* ent   = (const float*)d_in[5];
    const float* rel   = (const float*)d_in[6];
    const float* nv    = (const float*)d_in[7];

    int B     = in_sizes[0] / 3;
    int NEG   = in_sizes[1] / 3;
    int NR    = in_sizes[2];
    int ratio = NEG / B;                 // 8 for this dataset

    int threads = 32 * (ratio + 1);     // 288
    fused_kernel<<<B, threads>>>(pos, neg, rr1, rr2, rconf, ent, rel, nv, ratio, NR);
    final_reduce<<<1, 256>>>((float*)d_out, B, NEG);
}